// round 14
// baseline (speedup 1.0000x reference)
// R14: R10 (best, 2271us) + programmatic dependent launch (PDL) on every kernel edge
#include <cuda_runtime.h>
#include <cuda_bf16.h>
#include <cstdint>

#define NSTEP 16
#define NB 128
#define NE 512
#define NH 8
#define NIN 256
#define NOUT 128
#define NMEM 32769
#define NLAY 2

#define OFF_WIN 0
#define OFF_IPW 131072
#define OFF_AOW 1703936
#define OFF_FFW 2228224
#define WTOT    2752512
#define CONV_TOT 3276800      // WTOT + 16*128*256 (seq)

// gemm smem geometry (bf16 elements)
#define GS_ROW    72          // 64 data + 8 pad  (144B stride, 16B aligned)
#define GS_MAT    (64 * GS_ROW)        // 4608
#define GS_BUF    (4 * GS_MAT)         // 18432 elems = 36864 B
#define GS_BYTES  (2 * GS_BUF * 2)     // 73728 B dynamic smem

typedef __nv_bfloat16 bf16;

// ---- scratch ----
__device__ float g_X  [NSTEP * NB * NE];
__device__ float g_h  [NB * NSTEP * NE];
__device__ float g_qkv[NB * NSTEP * 3 * NE];
__device__ float g_tmp[NB * NSTEP * NE];
__device__ __align__(16) bf16 g_hh[NB * NSTEP * NE];
__device__ __align__(16) bf16 g_hl[NB * NSTEP * NE];
__device__ __align__(16) bf16 g_ah[NB * NSTEP * NE];
__device__ __align__(16) bf16 g_al[NB * NSTEP * NE];
__device__ __align__(16) bf16 g_sh[NSTEP * NB * NIN];
__device__ __align__(16) bf16 g_sl[NSTEP * NB * NIN];
__device__ __align__(16) bf16 g_wh[WTOT];
__device__ __align__(16) bf16 g_wl[WTOT];

// ---- PDL primitives (sm_90+, plain PTX to avoid header availability issues) ----
__device__ __forceinline__ void gdc_wait()   { asm volatile("griddepcontrol.wait;" ::: "memory"); }
__device__ __forceinline__ void gdc_launch() { asm volatile("griddepcontrol.launch_dependents;"); }

__device__ __forceinline__ uint32_t smem_u32(const void* p) {
    uint32_t a;
    asm("{ .reg .u64 t; cvta.to.shared.u64 t, %1; cvt.u32.u64 %0, t; }" : "=r"(a) : "l"(p));
    return a;
}

#define CP16(dst, src) \
    asm volatile("cp.async.cg.shared.global [%0], [%1], 16;" :: "r"(dst), "l"(src))
#define CP_COMMIT() asm volatile("cp.async.commit_group;")
#define CP_WAIT(n)  asm volatile("cp.async.wait_group %0;" :: "n"(n))

#define LDM4(r, addr) \
    asm volatile("ldmatrix.sync.aligned.m8n8.x4.shared.b16 {%0,%1,%2,%3}, [%4];" \
        : "=r"((r)[0]), "=r"((r)[1]), "=r"((r)[2]), "=r"((r)[3]) : "r"(addr))

#define MMA(d, a, b) \
    asm volatile("mma.sync.aligned.m16n8k16.row.col.f32.bf16.bf16.f32 " \
        "{%0,%1,%2,%3}, {%4,%5,%6,%7}, {%8,%9}, {%0,%1,%2,%3};" \
        : "+f"((d)[0]), "+f"((d)[1]), "+f"((d)[2]), "+f"((d)[3]) \
        : "r"((a)[0]), "r"((a)[1]), "r"((a)[2]), "r"((a)[3]), "r"((b)[0]), "r"((b)[1]))

__device__ __forceinline__ void split_store(size_t d, float v)
{
    bf16 h = __float2bfloat16(v);
    g_hh[d] = h;
    g_hl[d] = __float2bfloat16(v - __bfloat162float(h));
}

// ======================= tensor-core GEMM (64x64 tile, BK=64, cp.async) =====
// C[m,n] = sum_k (Ah+Al)[m,k]*(Wh+Wl)[n,k] + bias[n]  (3-term split)
// grid = (N/64, M/64), block = 256.  Row m -> (b=m/L, i=m%L).
__global__ __launch_bounds__(256) void gemm_tc_k(
    const bf16* __restrict__ Ah, const bf16* __restrict__ Al,
    const bf16* __restrict__ Wh, const bf16* __restrict__ Wl,
    const float* __restrict__ bias, float* __restrict__ C,
    int N, int K, int L, int slotA, int slotC)
{
    extern __shared__ __align__(16) bf16 sm[];
    const uint32_t sbase = smem_u32(sm);

    const int tid  = threadIdx.x;
    const int warp = tid >> 5;
    const int lane = tid & 31;
    const int bm = blockIdx.y << 6;
    const int bn = blockIdx.x << 6;

    const int r0  = tid >> 3;
    const int r1  = 32 + r0;
    const int k16 = tid & 7;

    const int gm0 = bm + r0, gm1 = bm + r1;
    const int ab0 = gm0 / L, ab1 = gm1 / L;
    const size_t aoff0 = (size_t)(ab0 * slotA + (gm0 - ab0 * L)) * K + k16 * 8;
    const size_t aoff1 = (size_t)(ab1 * slotA + (gm1 - ab1 * L)) * K + k16 * 8;
    const size_t woff0 = (size_t)(bn + r0) * K + k16 * 8;
    const size_t woff1 = (size_t)(bn + r1) * K + k16 * 8;

    const uint32_t dA0 = sbase + (0 * GS_MAT + r0 * GS_ROW + k16 * 8) * 2;
    const uint32_t dA1 = sbase + (0 * GS_MAT + r1 * GS_ROW + k16 * 8) * 2;
    const uint32_t dB0 = sbase + (1 * GS_MAT + r0 * GS_ROW + k16 * 8) * 2;
    const uint32_t dB1 = sbase + (1 * GS_MAT + r1 * GS_ROW + k16 * 8) * 2;
    const uint32_t dW0 = sbase + (2 * GS_MAT + r0 * GS_ROW + k16 * 8) * 2;
    const uint32_t dW1 = sbase + (2 * GS_MAT + r1 * GS_ROW + k16 * 8) * 2;
    const uint32_t dV0 = sbase + (3 * GS_MAT + r0 * GS_ROW + k16 * 8) * 2;
    const uint32_t dV1 = sbase + (3 * GS_MAT + r1 * GS_ROW + k16 * 8) * 2;

    const int warpM = (warp >> 1) << 4;
    const int warpN = (warp & 1) << 5;
    const int aRow = (lane & 15);
    const int aKof = (lane >> 4) << 3;
    const uint32_t adrAh = sbase + (0 * GS_MAT + (warpM + aRow) * GS_ROW + aKof) * 2;
    const uint32_t adrAl = sbase + (1 * GS_MAT + (warpM + aRow) * GS_ROW + aKof) * 2;
    const int bRow = (lane & 7) + ((lane >> 4) << 3);
    const int bKof = ((lane >> 3) & 1) << 3;
    const uint32_t adrWh0 = sbase + (2 * GS_MAT + (warpN + bRow) * GS_ROW + bKof) * 2;
    const uint32_t adrWh1 = adrWh0 + 16 * GS_ROW * 2;
    const uint32_t adrWl0 = sbase + (3 * GS_MAT + (warpN + bRow) * GS_ROW + bKof) * 2;
    const uint32_t adrWl1 = adrWl0 + 16 * GS_ROW * 2;

    float acc[4][4];
    #pragma unroll
    for (int nt = 0; nt < 4; nt++)
        #pragma unroll
        for (int j = 0; j < 4; j++) acc[nt][j] = 0.f;

    const int nc = K >> 6;

    // wait for predecessor's writes (A operands), then start pipeline
    gdc_wait();
    {
        CP16(dA0, Ah + aoff0); CP16(dA1, Ah + aoff1);
        CP16(dB0, Al + aoff0); CP16(dB1, Al + aoff1);
        CP16(dW0, Wh + woff0); CP16(dW1, Wh + woff1);
        CP16(dV0, Wl + woff0); CP16(dV1, Wl + woff1);
        CP_COMMIT();
    }

    for (int c = 0; c < nc; c++) {
        const uint32_t bufo = (c & 1) ? (uint32_t)(GS_BUF * 2) : 0u;
        if (c + 1 < nc) {
            const uint32_t nbo = ((c + 1) & 1) ? (uint32_t)(GS_BUF * 2) : 0u;
            const int ko = (c + 1) << 6;
            CP16(dA0 + nbo, Ah + aoff0 + ko); CP16(dA1 + nbo, Ah + aoff1 + ko);
            CP16(dB0 + nbo, Al + aoff0 + ko); CP16(dB1 + nbo, Al + aoff1 + ko);
            CP16(dW0 + nbo, Wh + woff0 + ko); CP16(dW1 + nbo, Wh + woff1 + ko);
            CP16(dV0 + nbo, Wl + woff0 + ko); CP16(dV1 + nbo, Wl + woff1 + ko);
            CP_COMMIT();
            CP_WAIT(1);
        } else {
            CP_WAIT(0);
        }
        __syncthreads();

        #pragma unroll
        for (int ks = 0; ks < 4; ks++) {
            const uint32_t kb = bufo + ks * 32;
            uint32_t ah[4], al[4];
            LDM4(ah, adrAh + kb);
            LDM4(al, adrAl + kb);
            uint32_t bh[4][2], bl[4][2];
            {
                uint32_t t[4];
                LDM4(t, adrWh0 + kb);
                bh[0][0] = t[0]; bh[0][1] = t[1]; bh[1][0] = t[2]; bh[1][1] = t[3];
                LDM4(t, adrWh1 + kb);
                bh[2][0] = t[0]; bh[2][1] = t[1]; bh[3][0] = t[2]; bh[3][1] = t[3];
                LDM4(t, adrWl0 + kb);
                bl[0][0] = t[0]; bl[0][1] = t[1]; bl[1][0] = t[2]; bl[1][1] = t[3];
                LDM4(t, adrWl1 + kb);
                bl[2][0] = t[0]; bl[2][1] = t[1]; bl[3][0] = t[2]; bl[3][1] = t[3];
            }
            #pragma unroll
            for (int nt = 0; nt < 4; nt++) {
                MMA(acc[nt], ah, bh[nt]);
                MMA(acc[nt], ah, bl[nt]);
                MMA(acc[nt], al, bh[nt]);
            }
        }
        __syncthreads();
    }

    // mainloop done: let the successor start ramping while we run the epilogue
    gdc_launch();

    const int cn = bn + warpN + ((lane & 3) << 1);
    #pragma unroll
    for (int half = 0; half < 2; half++) {
        const int m = bm + warpM + (lane >> 2) + half * 8;
        const int b = m / L;
        const int i = m - b * L;
        float* cp = C + (size_t)(b * slotC + i) * N + cn;
        #pragma unroll
        for (int nt = 0; nt < 4; nt++) {
            float2 o;
            o.x = acc[nt][half * 2 + 0] + bias[cn + nt * 8];
            o.y = acc[nt][half * 2 + 1] + bias[cn + nt * 8 + 1];
            *(float2*)(cp + nt * 8) = o;
        }
    }
}

// ======================= fp32 -> bf16 hi/lo (all weights + seq) =======================
__global__ void conv_all_k(const float* __restrict__ Win, const float* __restrict__ ipw,
                           const float* __restrict__ aow, const float* __restrict__ ffw,
                           const float* __restrict__ seq)
{
    gdc_wait();
    const int nth = gridDim.x * 256;
    for (int idx = blockIdx.x * 256 + threadIdx.x; idx < CONV_TOT; idx += nth) {
        if (idx < WTOT) {
            float x;
            if (idx < OFF_IPW)      x = Win[idx];
            else if (idx < OFF_AOW) x = ipw[idx - OFF_IPW];
            else if (idx < OFF_FFW) x = aow[idx - OFF_AOW];
            else                    x = ffw[idx - OFF_FFW];
            bf16 h = __float2bfloat16(x);
            g_wh[idx] = h;
            g_wl[idx] = __float2bfloat16(x - __bfloat162float(h));
        } else {
            int i2 = idx - WTOT;
            float x = seq[i2];
            bf16 h = __float2bfloat16(x);
            g_sh[i2] = h;
            g_sl[i2] = __float2bfloat16(x - __bfloat162float(h));
        }
    }
    gdc_launch();
}

__device__ __forceinline__ void scatter_one(int t, int j)
{
    int b = j >> 9, e = j & 511;
    float x = g_X[((size_t)t * NB + b) * NE + e];
    size_t d = ((size_t)b * NSTEP + t) * NE + e;
    g_h[d] = x;
    split_store(d, x);
}

__global__ void scatter_k(int t)
{
    gdc_wait();
    int idx = blockIdx.x * 256 + threadIdx.x;   // 128*512
    scatter_one(t, idx);
    gdc_launch();
}

// ---- outproj(t) + scatter(t+1), merged (disjoint h slots) ----
__global__ __launch_bounds__(256) void outscatter_k(
    int t, const float* __restrict__ Wout, const float* __restrict__ b_out,
    float* __restrict__ out, int do_scatter)
{
    gdc_wait();
    const int tot = NB * NOUT + (do_scatter ? NB * NE : 0);
    int idx = blockIdx.x * 256 + threadIdx.x;
    if (idx < tot) {
        if (idx < NB * NOUT) {
            int b = idx >> 7, n = idx & 127;
            const float4* hr = (const float4*)(g_h + ((size_t)b * NSTEP + t) * NE);
            const float4* wr = (const float4*)(Wout + (size_t)n * NE);
            float acc = 0.f;
            #pragma unroll 8
            for (int e = 0; e < 128; e++) {
                float4 a = hr[e], w = wr[e];
                acc += a.x * w.x + a.y * w.y + a.z * w.z + a.w * w.w;
            }
            out[((size_t)t * NB + b) * NOUT + n] = acc + b_out[n];
        } else {
            scatter_one(t + 1, idx - NB * NOUT);
        }
    }
    gdc_launch();
}

// ---- per (batch, head) attention; writes att as bf16 hi/lo ----
__global__ __launch_bounds__(256) void attn_k(int seqL)
{
    __shared__ float q_s[16][64], k_s[16][64], v_s[16][64];
    __shared__ float p_s[16][17];
    int blk = blockIdx.x; int b = blk >> 3; int hh = blk & 7;
    int tid = threadIdx.x;
    const float* base = g_qkv + (size_t)b * NSTEP * 1536 + hh * 64;
    gdc_wait();
    for (int e = tid; e < 1024; e += 256) {
        int i = e >> 6, d = e & 63;
        if (i < seqL) {
            const float* p = base + (size_t)i * 1536 + d;
            q_s[i][d] = p[0];
            k_s[i][d] = p[512];
            v_s[i][d] = p[1024];
        }
    }
    __syncthreads();
    gdc_launch();        // inputs consumed; successor may ramp
    int si = tid >> 4, sj = tid & 15;
    if (si < seqL && sj < seqL) {
        float s = 0.f;
        #pragma unroll
        for (int d = 0; d < 64; d++) s += q_s[si][d] * k_s[sj][d];
        p_s[si][sj] = s * 0.125f;
    }
    __syncthreads();
    if (tid < seqL) {
        float mx = -1e30f;
        for (int j = 0; j < seqL; j++) mx = fmaxf(mx, p_s[tid][j]);
        float sum = 0.f;
        for (int j = 0; j < seqL; j++) { float e = expf(p_s[tid][j] - mx); p_s[tid][j] = e; sum += e; }
        float inv = 1.f / sum;
        for (int j = 0; j < seqL; j++) p_s[tid][j] *= inv;
    }
    __syncthreads();
    int qi = tid >> 4, d0 = (tid & 15) << 2;
    if (qi < seqL) {
        float o[4] = {0, 0, 0, 0};
        for (int j = 0; j < seqL; j++) {
            float p = p_s[qi][j];
            o[0] += p * v_s[j][d0];     o[1] += p * v_s[j][d0 + 1];
            o[2] += p * v_s[j][d0 + 2]; o[3] += p * v_s[j][d0 + 3];
        }
        size_t d = ((size_t)b * NSTEP + qi) * NE + hh * 64 + d0;
        #pragma unroll
        for (int k = 0; k < 4; k++) {
            bf16 h = __float2bfloat16(o[k]);
            g_ah[d + k] = h;
            g_al[d + k] = __float2bfloat16(o[k] - __bfloat162float(h));
        }
    }
}

// ---- h = LN(h + tmp)*scale + bias  (+ bf16 split) ----
__global__ __launch_bounds__(256) void resid_ln_k(
    const float* __restrict__ sc, const float* __restrict__ bi, int seqL)
{
    int r = blockIdx.x;
    int b = r / seqL; int i = r - b * seqL;
    size_t rowo = ((size_t)b * NSTEP + i) * NE;
    float* hp = g_h + rowo;
    const float* tp = g_tmp + rowo;
    int tid = threadIdx.x;
    gdc_wait();
    float y0 = hp[tid] + tp[tid];
    float y1 = hp[tid + 256] + tp[tid + 256];
    gdc_launch();        // inputs read; successor may ramp
    float s = y0 + y1, ss = y0 * y0 + y1 * y1;
    __shared__ float shs[8], shq[8];
    __shared__ float mu_sh, inv_sh;
    int lane = tid & 31, w = tid >> 5;
    #pragma unroll
    for (int o = 16; o > 0; o >>= 1) {
        s  += __shfl_down_sync(0xffffffffu, s, o);
        ss += __shfl_down_sync(0xffffffffu, ss, o);
    }
    if (lane == 0) { shs[w] = s; shq[w] = ss; }
    __syncthreads();
    if (tid == 0) {
        float ts = 0, tq = 0;
        #pragma unroll
        for (int k = 0; k < 8; k++) { ts += shs[k]; tq += shq[k]; }
        float mu = ts * (1.f / 512.f);
        float var = tq * (1.f / 512.f) - mu * mu;
        mu_sh = mu; inv_sh = rsqrtf(var + 1e-5f);
    }
    __syncthreads();
    float mu = mu_sh, inv = inv_sh;
    float v0 = (y0 - mu) * inv * sc[tid]       + bi[tid];
    float v1 = (y1 - mu) * inv * sc[tid + 256] + bi[tid + 256];
    hp[tid] = v0; hp[tid + 256] = v1;
    split_store(rowo + tid, v0);
    split_store(rowo + tid + 256, v1);
}

// ---- write new_h ----
__global__ void assemble_k(const float* __restrict__ hstate, float* __restrict__ outh)
{
    gdc_wait();
    int idx = blockIdx.x * 256 + threadIdx.x;
    if (idx >= NB * NMEM) return;
    int b = idx / NMEM; int j = idx - b * NMEM;
    float v;
    if (j < NSTEP * NE)      v = g_h[(size_t)b * NSTEP * NE + j];
    else if (j < NMEM - 1)   v = hstate[idx];
    else                     v = (float)((int)hstate[idx] + NSTEP);
    outh[idx] = v;
}

// ======================= host: PDL launch helper =======================
template <typename F, typename... Args>
static inline void launch_pdl(F f, dim3 grid, dim3 block, size_t shmem, Args... args)
{
    cudaLaunchConfig_t cfg = {};
    cfg.gridDim = grid;
    cfg.blockDim = block;
    cfg.dynamicSmemBytes = shmem;
    cfg.stream = 0;
    cudaLaunchAttribute at[1];
    at[0].id = cudaLaunchAttributeProgrammaticStreamSerialization;
    at[0].val.programmaticStreamSerializationAllowed = 1;
    cfg.attrs = at;
    cfg.numAttrs = 1;
    cudaLaunchKernelEx(&cfg, f, args...);
}

extern "C" void kernel_launch(void* const* d_in, const int* in_sizes, int n_in,
                              void* d_out, int out_size)
{
    (void)in_sizes; (void)n_in; (void)out_size;
    const float* seq   = (const float*)d_in[0];
    const float* hst   = (const float*)d_in[1];
    const float* Win   = (const float*)d_in[2];
    const float* b_in  = (const float*)d_in[3];
    const float* Wout  = (const float*)d_in[4];
    const float* b_out = (const float*)d_in[5];
    const float* ipw   = (const float*)d_in[6];
    const float* ipb   = (const float*)d_in[7];
    const float* aow   = (const float*)d_in[8];
    const float* aob   = (const float*)d_in[9];
    const float* l1s   = (const float*)d_in[10];
    const float* l1b   = (const float*)d_in[11];
    const float* l2s   = (const float*)d_in[12];
    const float* l2b   = (const float*)d_in[13];
    const float* ffw   = (const float*)d_in[14];
    const float* ffb   = (const float*)d_in[15];
    float* out = (float*)d_out;

    cudaFuncSetAttribute(gemm_tc_k, cudaFuncAttributeMaxDynamicSharedMemorySize, GS_BYTES);

    float *pX, *pqkv, *ptmp;
    bf16 *phh, *phl, *pah, *pal, *psh, *psl, *pwh, *pwl;
    cudaGetSymbolAddress((void**)&pX,   g_X);
    cudaGetSymbolAddress((void**)&pqkv, g_qkv);
    cudaGetSymbolAddress((void**)&ptmp, g_tmp);
    cudaGetSymbolAddress((void**)&phh,  g_hh);
    cudaGetSymbolAddress((void**)&phl,  g_hl);
    cudaGetSymbolAddress((void**)&pah,  g_ah);
    cudaGetSymbolAddress((void**)&pal,  g_al);
    cudaGetSymbolAddress((void**)&psh,  g_sh);
    cudaGetSymbolAddress((void**)&psl,  g_sl);
    cudaGetSymbolAddress((void**)&pwh,  g_wh);
    cudaGetSymbolAddress((void**)&pwl,  g_wl);

    launch_pdl(conv_all_k, dim3(512), dim3(256), 0, Win, ipw, aow, ffw, seq);

    // X = seq @ Win^T + b_in   (M=2048 contiguous, N=512, K=256)
    launch_pdl(gemm_tc_k, dim3(NE / 64, (NSTEP * NB) / 64), dim3(256), (size_t)GS_BYTES,
               (const bf16*)psh, (const bf16*)psl,
               (const bf16*)(pwh + OFF_WIN), (const bf16*)(pwl + OFF_WIN),
               b_in, pX, NE, NIN, NSTEP * NB, 0, 0);

    launch_pdl(scatter_k, dim3((NB * NE) / 256), dim3(256), 0, 0);

    for (int t = 0; t < NSTEP; t++) {
        int Lq = t + 1;
        int mt = (NB * Lq) / 64;      // 2*Lq

        for (int l = 0; l < NLAY; l++) {
            launch_pdl(gemm_tc_k, dim3(3 * NE / 64, mt), dim3(256), (size_t)GS_BYTES,
                       (const bf16*)phh, (const bf16*)phl,
                       (const bf16*)(pwh + OFF_IPW + (size_t)l * 3 * NE * NE),
                       (const bf16*)(pwl + OFF_IPW + (size_t)l * 3 * NE * NE),
                       (const float*)(ipb + l * 3 * NE), pqkv,
                       3 * NE, NE, Lq, NSTEP, NSTEP);
            launch_pdl(attn_k, dim3(NB * NH), dim3(256), 0, Lq);
            launch_pdl(gemm_tc_k, dim3(NE / 64, mt), dim3(256), (size_t)GS_BYTES,
                       (const bf16*)pah, (const bf16*)pal,
                       (const bf16*)(pwh + OFF_AOW + (size_t)l * NE * NE),
                       (const bf16*)(pwl + OFF_AOW + (size_t)l * NE * NE),
                       (const float*)(aob + l * NE), ptmp,
                       NE, NE, Lq, NSTEP, NSTEP);
            launch_pdl(resid_ln_k, dim3(NB * Lq), dim3(256), 0,
                       (const float*)(l1s + l * NE), (const float*)(l1b + l * NE), Lq);
            launch_pdl(gemm_tc_k, dim3(NE / 64, mt), dim3(256), (size_t)GS_BYTES,
                       (const bf16*)phh, (const bf16*)phl,
                       (const bf16*)(pwh + OFF_FFW + (size_t)l * NE * NE),
                       (const bf16*)(pwl + OFF_FFW + (size_t)l * NE * NE),
                       (const float*)(ffb + l * NE), ptmp,
                       NE, NE, Lq, NSTEP, NSTEP);
            launch_pdl(resid_ln_k, dim3(NB * Lq), dim3(256), 0,
                       (const float*)(l2s + l * NE), (const float*)(l2b + l * NE), Lq);
        }
        int do_sc = (t + 1 < NSTEP) ? 1 : 0;
        int tot = NB * NOUT + (do_sc ? NB * NE : 0);
        launch_pdl(outscatter_k, dim3((tot + 255) / 256), dim3(256), 0,
                   t, Wout, b_out, out, do_sc);
    }

    launch_pdl(assemble_k, dim3((NB * NMEM + 255) / 256), dim3(256), 0,
               hst, out + NSTEP * NB * NOUT);
}

// round 16
// speedup vs baseline: 2.0617x; 2.0617x over previous
// R16: resubmit of R15 (infra failure, not kernel) — attn bank-fix + sync-free fusions
#include <cuda_runtime.h>
#include <cuda_bf16.h>
#include <cstdint>

#define NSTEP 16
#define NB 128
#define NE 512
#define NH 8
#define NIN 256
#define NOUT 128
#define NMEM 32769
#define NLAY 2

#define OFF_WIN 0
#define OFF_IPW 131072
#define OFF_AOW 1703936
#define OFF_FFW 2228224
#define WTOT    2752512
#define CONV_TOT 3276800      // WTOT + 16*128*256 (seq)

// gemm smem geometry (bf16 elements)
#define GS_ROW    72          // 64 data + 8 pad  (144B stride, 16B aligned)
#define GS_MAT    (64 * GS_ROW)
#define GS_BUF    (4 * GS_MAT)
#define GS_BYTES  (2 * GS_BUF * 2)     // 73728 B dynamic smem

#define EP_NONE 0
#define EP_SC0  1     // X gemm: rows m<NB also scattered into h slot 0

typedef __nv_bfloat16 bf16;

// ---- scratch ----
__device__ float g_X  [NSTEP * NB * NE];
__device__ float g_h  [NB * NSTEP * NE];
__device__ float g_qkv[NB * NSTEP * 3 * NE];
__device__ float g_tmp[NB * NSTEP * NE];
__device__ __align__(16) bf16 g_hh[NB * NSTEP * NE];
__device__ __align__(16) bf16 g_hl[NB * NSTEP * NE];
__device__ __align__(16) bf16 g_ah[NB * NSTEP * NE];
__device__ __align__(16) bf16 g_al[NB * NSTEP * NE];
__device__ __align__(16) bf16 g_sh[NSTEP * NB * NIN];
__device__ __align__(16) bf16 g_sl[NSTEP * NB * NIN];
__device__ __align__(16) bf16 g_wh[WTOT];
__device__ __align__(16) bf16 g_wl[WTOT];

__device__ __forceinline__ uint32_t smem_u32(const void* p) {
    uint32_t a;
    asm("{ .reg .u64 t; cvta.to.shared.u64 t, %1; cvt.u32.u64 %0, t; }" : "=r"(a) : "l"(p));
    return a;
}

#define CP16(dst, src) \
    asm volatile("cp.async.cg.shared.global [%0], [%1], 16;" :: "r"(dst), "l"(src))
#define CP_COMMIT() asm volatile("cp.async.commit_group;")
#define CP_WAIT(n)  asm volatile("cp.async.wait_group %0;" :: "n"(n))

#define LDM4(r, addr) \
    asm volatile("ldmatrix.sync.aligned.m8n8.x4.shared.b16 {%0,%1,%2,%3}, [%4];" \
        : "=r"((r)[0]), "=r"((r)[1]), "=r"((r)[2]), "=r"((r)[3]) : "r"(addr))

#define MMA(d, a, b) \
    asm volatile("mma.sync.aligned.m16n8k16.row.col.f32.bf16.bf16.f32 " \
        "{%0,%1,%2,%3}, {%4,%5,%6,%7}, {%8,%9}, {%0,%1,%2,%3};" \
        : "+f"((d)[0]), "+f"((d)[1]), "+f"((d)[2]), "+f"((d)[3]) \
        : "r"((a)[0]), "r"((a)[1]), "r"((a)[2]), "r"((a)[3]), "r"((b)[0]), "r"((b)[1]))

__device__ __forceinline__ void split_store(size_t d, float v)
{
    bf16 h = __float2bfloat16(v);
    g_hh[d] = h;
    g_hl[d] = __float2bfloat16(v - __bfloat162float(h));
}

// ======================= tensor-core GEMM (64x64 tile, BK=64, cp.async) =====
// C[m,n] = sum_k (Ah+Al)[m,k]*(Wh+Wl)[n,k] + bias[n]  (3-term split)
__global__ __launch_bounds__(256) void gemm_tc_k(
    const bf16* __restrict__ Ah, const bf16* __restrict__ Al,
    const bf16* __restrict__ Wh, const bf16* __restrict__ Wl,
    const float* __restrict__ bias, float* __restrict__ C,
    int N, int K, int L, int slotA, int slotC, int mode)
{
    extern __shared__ __align__(16) bf16 sm[];
    const uint32_t sbase = smem_u32(sm);

    const int tid  = threadIdx.x;
    const int warp = tid >> 5;
    const int lane = tid & 31;
    const int bm = blockIdx.y << 6;
    const int bn = blockIdx.x << 6;

    const int r0  = tid >> 3;
    const int r1  = 32 + r0;
    const int k16 = tid & 7;

    const int gm0 = bm + r0, gm1 = bm + r1;
    const int ab0 = gm0 / L, ab1 = gm1 / L;
    const size_t aoff0 = (size_t)(ab0 * slotA + (gm0 - ab0 * L)) * K + k16 * 8;
    const size_t aoff1 = (size_t)(ab1 * slotA + (gm1 - ab1 * L)) * K + k16 * 8;
    const size_t woff0 = (size_t)(bn + r0) * K + k16 * 8;
    const size_t woff1 = (size_t)(bn + r1) * K + k16 * 8;

    const uint32_t dA0 = sbase + (0 * GS_MAT + r0 * GS_ROW + k16 * 8) * 2;
    const uint32_t dA1 = sbase + (0 * GS_MAT + r1 * GS_ROW + k16 * 8) * 2;
    const uint32_t dB0 = sbase + (1 * GS_MAT + r0 * GS_ROW + k16 * 8) * 2;
    const uint32_t dB1 = sbase + (1 * GS_MAT + r1 * GS_ROW + k16 * 8) * 2;
    const uint32_t dW0 = sbase + (2 * GS_MAT + r0 * GS_ROW + k16 * 8) * 2;
    const uint32_t dW1 = sbase + (2 * GS_MAT + r1 * GS_ROW + k16 * 8) * 2;
    const uint32_t dV0 = sbase + (3 * GS_MAT + r0 * GS_ROW + k16 * 8) * 2;
    const uint32_t dV1 = sbase + (3 * GS_MAT + r1 * GS_ROW + k16 * 8) * 2;

    const int warpM = (warp >> 1) << 4;
    const int warpN = (warp & 1) << 5;
    const int aRow = (lane & 15);
    const int aKof = (lane >> 4) << 3;
    const uint32_t adrAh = sbase + (0 * GS_MAT + (warpM + aRow) * GS_ROW + aKof) * 2;
    const uint32_t adrAl = sbase + (1 * GS_MAT + (warpM + aRow) * GS_ROW + aKof) * 2;
    const int bRow = (lane & 7) + ((lane >> 4) << 3);
    const int bKof = ((lane >> 3) & 1) << 3;
    const uint32_t adrWh0 = sbase + (2 * GS_MAT + (warpN + bRow) * GS_ROW + bKof) * 2;
    const uint32_t adrWh1 = adrWh0 + 16 * GS_ROW * 2;
    const uint32_t adrWl0 = sbase + (3 * GS_MAT + (warpN + bRow) * GS_ROW + bKof) * 2;
    const uint32_t adrWl1 = adrWl0 + 16 * GS_ROW * 2;

    float acc[4][4];
    #pragma unroll
    for (int nt = 0; nt < 4; nt++)
        #pragma unroll
        for (int j = 0; j < 4; j++) acc[nt][j] = 0.f;

    const int nc = K >> 6;

    {
        CP16(dA0, Ah + aoff0); CP16(dA1, Ah + aoff1);
        CP16(dB0, Al + aoff0); CP16(dB1, Al + aoff1);
        CP16(dW0, Wh + woff0); CP16(dW1, Wh + woff1);
        CP16(dV0, Wl + woff0); CP16(dV1, Wl + woff1);
        CP_COMMIT();
    }

    for (int c = 0; c < nc; c++) {
        const uint32_t bufo = (c & 1) ? (uint32_t)(GS_BUF * 2) : 0u;
        if (c + 1 < nc) {
            const uint32_t nbo = ((c + 1) & 1) ? (uint32_t)(GS_BUF * 2) : 0u;
            const int ko = (c + 1) << 6;
            CP16(dA0 + nbo, Ah + aoff0 + ko); CP16(dA1 + nbo, Ah + aoff1 + ko);
            CP16(dB0 + nbo, Al + aoff0 + ko); CP16(dB1 + nbo, Al + aoff1 + ko);
            CP16(dW0 + nbo, Wh + woff0 + ko); CP16(dW1 + nbo, Wh + woff1 + ko);
            CP16(dV0 + nbo, Wl + woff0 + ko); CP16(dV1 + nbo, Wl + woff1 + ko);
            CP_COMMIT();
            CP_WAIT(1);
        } else {
            CP_WAIT(0);
        }
        __syncthreads();

        #pragma unroll
        for (int ks = 0; ks < 4; ks++) {
            const uint32_t kb = bufo + ks * 32;
            uint32_t ah[4], al[4];
            LDM4(ah, adrAh + kb);
            LDM4(al, adrAl + kb);
            uint32_t bh[4][2], bl[4][2];
            {
                uint32_t t[4];
                LDM4(t, adrWh0 + kb);
                bh[0][0] = t[0]; bh[0][1] = t[1]; bh[1][0] = t[2]; bh[1][1] = t[3];
                LDM4(t, adrWh1 + kb);
                bh[2][0] = t[0]; bh[2][1] = t[1]; bh[3][0] = t[2]; bh[3][1] = t[3];
                LDM4(t, adrWl0 + kb);
                bl[0][0] = t[0]; bl[0][1] = t[1]; bl[1][0] = t[2]; bl[1][1] = t[3];
                LDM4(t, adrWl1 + kb);
                bl[2][0] = t[0]; bl[2][1] = t[1]; bl[3][0] = t[2]; bl[3][1] = t[3];
            }
            #pragma unroll
            for (int nt = 0; nt < 4; nt++) {
                MMA(acc[nt], ah, bh[nt]);
                MMA(acc[nt], ah, bl[nt]);
                MMA(acc[nt], al, bh[nt]);
            }
        }
        __syncthreads();
    }

    // ---- epilogue ----
    const int cn = bn + warpN + ((lane & 3) << 1);
    #pragma unroll
    for (int half = 0; half < 2; half++) {
        const int m = bm + warpM + (lane >> 2) + half * 8;
        const int b = m / L;
        const int i = m - b * L;
        float* cp = C + (size_t)(b * slotC + i) * N + cn;
        #pragma unroll
        for (int nt = 0; nt < 4; nt++) {
            float2 o;
            o.x = acc[nt][half * 2 + 0] + bias[cn + nt * 8];
            o.y = acc[nt][half * 2 + 1] + bias[cn + nt * 8 + 1];
            *(float2*)(cp + nt * 8) = o;
            if (mode == EP_SC0 && m < NB) {
                // row m = (t=0, b=m): scatter into h slot 0 + bf16 split
                size_t d = (size_t)m * NSTEP * NE + cn + nt * 8;
                g_h[d] = o.x; g_h[d + 1] = o.y;
                split_store(d, o.x); split_store(d + 1, o.y);
            }
        }
    }
}

// ======================= fp32 -> bf16 hi/lo (all weights + seq) =======================
__global__ void conv_all_k(const float* __restrict__ Win, const float* __restrict__ ipw,
                           const float* __restrict__ aow, const float* __restrict__ ffw,
                           const float* __restrict__ seq)
{
    const int nth = gridDim.x * 256;
    for (int idx = blockIdx.x * 256 + threadIdx.x; idx < CONV_TOT; idx += nth) {
        if (idx < WTOT) {
            float x;
            if (idx < OFF_IPW)      x = Win[idx];
            else if (idx < OFF_AOW) x = ipw[idx - OFF_IPW];
            else if (idx < OFF_FFW) x = aow[idx - OFF_AOW];
            else                    x = ffw[idx - OFF_FFW];
            bf16 h = __float2bfloat16(x);
            g_wh[idx] = h;
            g_wl[idx] = __float2bfloat16(x - __bfloat162float(h));
        } else {
            int i2 = idx - WTOT;
            float x = seq[i2];
            bf16 h = __float2bfloat16(x);
            g_sh[i2] = h;
            g_sl[i2] = __float2bfloat16(x - __bfloat162float(h));
        }
    }
}

__device__ __forceinline__ void scatter_one(int t, int j)
{
    int b = j >> 9, e = j & 511;
    float x = g_X[((size_t)t * NB + b) * NE + e];
    size_t d = ((size_t)b * NSTEP + t) * NE + e;
    g_h[d] = x;
    split_store(d, x);
}

// ---- per (batch, head) attention; rows padded to 65 floats (bank-conflict-free) ----
__global__ __launch_bounds__(256) void attn_k(int seqL)
{
    __shared__ float q_s[16][65], k_s[16][65], v_s[16][65];
    __shared__ float p_s[16][17];
    int blk = blockIdx.x; int b = blk >> 3; int hh = blk & 7;
    int tid = threadIdx.x;
    const float* base = g_qkv + (size_t)b * NSTEP * 1536 + hh * 64;
    for (int e = tid; e < 1024; e += 256) {
        int i = e >> 6, d = e & 63;
        if (i < seqL) {
            const float* p = base + (size_t)i * 1536 + d;
            q_s[i][d] = p[0];
            k_s[i][d] = p[512];
            v_s[i][d] = p[1024];
        }
    }
    __syncthreads();
    int si = tid >> 4, sj = tid & 15;
    if (si < seqL && sj < seqL) {
        float s = 0.f;
        #pragma unroll
        for (int d = 0; d < 64; d++) s += q_s[si][d] * k_s[sj][d];
        p_s[si][sj] = s * 0.125f;
    }
    __syncthreads();
    if (tid < seqL) {
        float mx = -1e30f;
        for (int j = 0; j < seqL; j++) mx = fmaxf(mx, p_s[tid][j]);
        float sum = 0.f;
        for (int j = 0; j < seqL; j++) { float e = expf(p_s[tid][j] - mx); p_s[tid][j] = e; sum += e; }
        float inv = 1.f / sum;
        for (int j = 0; j < seqL; j++) p_s[tid][j] *= inv;
    }
    __syncthreads();
    int qi = tid >> 4, d0 = (tid & 15) << 2;
    if (qi < seqL) {
        float o[4] = {0, 0, 0, 0};
        for (int j = 0; j < seqL; j++) {
            float p = p_s[qi][j];
            o[0] += p * v_s[j][d0];     o[1] += p * v_s[j][d0 + 1];
            o[2] += p * v_s[j][d0 + 2]; o[3] += p * v_s[j][d0 + 3];
        }
        size_t d = ((size_t)b * NSTEP + qi) * NE + hh * 64 + d0;
        #pragma unroll
        for (int k = 0; k < 4; k++) {
            bf16 h = __float2bfloat16(o[k]);
            g_ah[d + k] = h;
            g_al[d + k] = __float2bfloat16(o[k] - __bfloat162float(h));
        }
    }
}

// ---- h = LN(h + tmp)*scale + bias (+ split); optional fused outproj / scatter ----
// fuse_out: rows with i==t also compute out[t,b,:] (512-dot from smem rowbuf).
// extra 64 CTAs (r >= NB*seqL, only when do_scatter) scatter x_{t+1} into slot t+1.
__global__ __launch_bounds__(256) void resid_ln_k(
    const float* __restrict__ sc, const float* __restrict__ bi, int seqL,
    int fuse_out, int t, int do_scatter,
    const float* __restrict__ Wout, const float* __restrict__ b_out,
    float* __restrict__ out)
{
    const int tid = threadIdx.x;
    const int r = blockIdx.x;
    const int nrows = NB * seqL;
    if (r >= nrows) {
        for (int e = (r - nrows) * 256 + tid; e < NB * NE; e += 64 * 256)
            scatter_one(t + 1, e);
        return;
    }
    int b = r / seqL; int i = r - b * seqL;
    size_t rowo = ((size_t)b * NSTEP + i) * NE;
    float* hp = g_h + rowo;
    const float* tp = g_tmp + rowo;
    float y0 = hp[tid] + tp[tid];
    float y1 = hp[tid + 256] + tp[tid + 256];
    float s = y0 + y1, ss = y0 * y0 + y1 * y1;
    __shared__ float shs[8], shq[8];
    __shared__ float mu_sh, inv_sh;
    __shared__ __align__(16) float rowbuf[512];
    int lane = tid & 31, w = tid >> 5;
    #pragma unroll
    for (int o = 16; o > 0; o >>= 1) {
        s  += __shfl_down_sync(0xffffffffu, s, o);
        ss += __shfl_down_sync(0xffffffffu, ss, o);
    }
    if (lane == 0) { shs[w] = s; shq[w] = ss; }
    __syncthreads();
    if (tid == 0) {
        float ts = 0, tq = 0;
        #pragma unroll
        for (int k = 0; k < 8; k++) { ts += shs[k]; tq += shq[k]; }
        float mu = ts * (1.f / 512.f);
        float var = tq * (1.f / 512.f) - mu * mu;
        mu_sh = mu; inv_sh = rsqrtf(var + 1e-5f);
    }
    __syncthreads();
    float mu = mu_sh, inv = inv_sh;
    float v0 = (y0 - mu) * inv * sc[tid]       + bi[tid];
    float v1 = (y1 - mu) * inv * sc[tid + 256] + bi[tid + 256];
    hp[tid] = v0; hp[tid + 256] = v1;
    split_store(rowo + tid, v0);
    split_store(rowo + tid + 256, v1);

    if (fuse_out && i == t) {
        rowbuf[tid] = v0; rowbuf[tid + 256] = v1;
        __syncthreads();
        if (tid < NOUT) {
            const float4* wr = (const float4*)(Wout + (size_t)tid * NE);
            const float4* rb = (const float4*)rowbuf;
            float acc = 0.f;
            #pragma unroll 8
            for (int e = 0; e < 128; e++) {
                float4 aa = rb[e], ww = wr[e];
                acc += aa.x * ww.x + aa.y * ww.y + aa.z * ww.z + aa.w * ww.w;
            }
            out[((size_t)t * NB + b) * NOUT + tid] = acc + b_out[tid];
        }
    }
}

// ---- write new_h ----
__global__ void assemble_k(const float* __restrict__ hstate, float* __restrict__ outh)
{
    int idx = blockIdx.x * 256 + threadIdx.x;
    if (idx >= NB * NMEM) return;
    int b = idx / NMEM; int j = idx - b * NMEM;
    float v;
    if (j < NSTEP * NE)      v = g_h[(size_t)b * NSTEP * NE + j];
    else if (j < NMEM - 1)   v = hstate[idx];
    else                     v = (float)((int)hstate[idx] + NSTEP);
    outh[idx] = v;
}

extern "C" void kernel_launch(void* const* d_in, const int* in_sizes, int n_in,
                              void* d_out, int out_size)
{
    (void)in_sizes; (void)n_in; (void)out_size;
    const float* seq   = (const float*)d_in[0];
    const float* hst   = (const float*)d_in[1];
    const float* Win   = (const float*)d_in[2];
    const float* b_in  = (const float*)d_in[3];
    const float* Wout  = (const float*)d_in[4];
    const float* b_out = (const float*)d_in[5];
    const float* ipw   = (const float*)d_in[6];
    const float* ipb   = (const float*)d_in[7];
    const float* aow   = (const float*)d_in[8];
    const float* aob   = (const float*)d_in[9];
    const float* l1s   = (const float*)d_in[10];
    const float* l1b   = (const float*)d_in[11];
    const float* l2s   = (const float*)d_in[12];
    const float* l2b   = (const float*)d_in[13];
    const float* ffw   = (const float*)d_in[14];
    const float* ffb   = (const float*)d_in[15];
    float* out = (float*)d_out;

    cudaFuncSetAttribute(gemm_tc_k, cudaFuncAttributeMaxDynamicSharedMemorySize, GS_BYTES);

    float *pX, *pqkv, *ptmp;
    bf16 *phh, *phl, *pah, *pal, *psh, *psl, *pwh, *pwl;
    cudaGetSymbolAddress((void**)&pX,   g_X);
    cudaGetSymbolAddress((void**)&pqkv, g_qkv);
    cudaGetSymbolAddress((void**)&ptmp, g_tmp);
    cudaGetSymbolAddress((void**)&phh,  g_hh);
    cudaGetSymbolAddress((void**)&phl,  g_hl);
    cudaGetSymbolAddress((void**)&pah,  g_ah);
    cudaGetSymbolAddress((void**)&pal,  g_al);
    cudaGetSymbolAddress((void**)&psh,  g_sh);
    cudaGetSymbolAddress((void**)&psl,  g_sl);
    cudaGetSymbolAddress((void**)&pwh,  g_wh);
    cudaGetSymbolAddress((void**)&pwl,  g_wl);

    conv_all_k<<<512, 256>>>(Win, ipw, aow, ffw, seq);

    // X = seq @ Win^T + b_in (M=2048 contiguous, N=512, K=256) + scatter(0) fused
    gemm_tc_k<<<dim3(NE / 64, (NSTEP * NB) / 64), 256, GS_BYTES>>>(
        psh, psl, pwh + OFF_WIN, pwl + OFF_WIN, b_in, pX,
        NE, NIN, NSTEP * NB, 0, 0, EP_SC0);

    for (int t = 0; t < NSTEP; t++) {
        int Lq = t + 1;
        int mt = (NB * Lq) / 64;      // 2*Lq

        for (int l = 0; l < NLAY; l++) {
            gemm_tc_k<<<dim3(3 * NE / 64, mt), 256, GS_BYTES>>>(
                phh, phl, pwh + OFF_IPW + (size_t)l * 3 * NE * NE,
                pwl + OFF_IPW + (size_t)l * 3 * NE * NE,
                ipb + l * 3 * NE, pqkv, 3 * NE, NE, Lq, NSTEP, NSTEP, EP_NONE);
            attn_k<<<NB * NH, 256>>>(Lq);
            gemm_tc_k<<<dim3(NE / 64, mt), 256, GS_BYTES>>>(
                pah, pal, pwh + OFF_AOW + (size_t)l * NE * NE,
                pwl + OFF_AOW + (size_t)l * NE * NE,
                aob + l * NE, ptmp, NE, NE, Lq, NSTEP, NSTEP, EP_NONE);
            resid_ln_k<<<NB * Lq, 256>>>(l1s + l * NE, l1b + l * NE, Lq,
                                         0, t, 0, nullptr, nullptr, nullptr);
            gemm_tc_k<<<dim3(NE / 64, mt), 256, GS_BYTES>>>(
                phh, phl, pwh + OFF_FFW + (size_t)l * NE * NE,
                pwl + OFF_FFW + (size_t)l * NE * NE,
                ffb + l * NE, ptmp, NE, NE, Lq, NSTEP, NSTEP, EP_NONE);
            // LN2: on layer 1, fuse outproj(t) (+ scatter(t+1) via 64 extra CTAs)
            int fo = (l == 1) ? 1 : 0;
            int dsc = (l == 1 && t + 1 < NSTEP) ? 1 : 0;
            resid_ln_k<<<NB * Lq + (dsc ? 64 : 0), 256>>>(
                l2s + l * NE, l2b + l * NE, Lq, fo, t, dsc, Wout, b_out, out);
        }
    }

    assemble_k<<<(NB * NMEM + 255) / 256, 256>>>(hst, out + NSTEP * NB * NOUT);
}

// round 17
// speedup vs baseline: 2.4596x; 1.1930x over previous
// R17: fp16 2-term split (A=hi+lo fp16, W=single fp16) — 8 MMA/slice instead of 12
#include <cuda_runtime.h>
#include <cuda_fp16.h>
#include <cstdint>

#define NSTEP 16
#define NB 128
#define NE 512
#define NH 8
#define NIN 256
#define NOUT 128
#define NMEM 32769
#define NLAY 2

#define OFF_WIN 0
#define OFF_IPW 131072
#define OFF_AOW 1703936
#define OFF_FFW 2228224
#define WTOT    2752512
#define CONV_TOT 3276800      // WTOT + 16*128*256 (seq)

// gemm smem geometry (fp16 elements): mats 0=Ah, 1=Al, 2=W
#define GS_ROW    72          // 64 data + 8 pad (144B stride, 16B aligned)
#define GS_MAT    (64 * GS_ROW)
#define GS_BUF    (3 * GS_MAT)
#define GS_BYTES  (2 * GS_BUF * 2)     // 55296 B dynamic smem

#define EP_NONE 0
#define EP_SC0  1     // X gemm: rows m<NB also scattered into h slot 0

typedef __half f16;

// ---- scratch ----
__device__ float g_X  [NSTEP * NB * NE];
__device__ float g_h  [NB * NSTEP * NE];
__device__ float g_qkv[NB * NSTEP * 3 * NE];
__device__ float g_tmp[NB * NSTEP * NE];
__device__ __align__(16) f16 g_hh[NB * NSTEP * NE];     // h hi (fp16)
__device__ __align__(16) f16 g_hl[NB * NSTEP * NE];     // h lo
__device__ __align__(16) f16 g_ah[NB * NSTEP * NE];     // att hi
__device__ __align__(16) f16 g_al[NB * NSTEP * NE];     // att lo
__device__ __align__(16) f16 g_sh[NSTEP * NB * NIN];    // seq hi
__device__ __align__(16) f16 g_sl[NSTEP * NB * NIN];    // seq lo
__device__ __align__(16) f16 g_w [WTOT];                // weights (single fp16)

__device__ __forceinline__ uint32_t smem_u32(const void* p) {
    uint32_t a;
    asm("{ .reg .u64 t; cvta.to.shared.u64 t, %1; cvt.u32.u64 %0, t; }" : "=r"(a) : "l"(p));
    return a;
}

#define CP16(dst, src) \
    asm volatile("cp.async.cg.shared.global [%0], [%1], 16;" :: "r"(dst), "l"(src))
#define CP_COMMIT() asm volatile("cp.async.commit_group;")
#define CP_WAIT(n)  asm volatile("cp.async.wait_group %0;" :: "n"(n))

#define LDM4(r, addr) \
    asm volatile("ldmatrix.sync.aligned.m8n8.x4.shared.b16 {%0,%1,%2,%3}, [%4];" \
        : "=r"((r)[0]), "=r"((r)[1]), "=r"((r)[2]), "=r"((r)[3]) : "r"(addr))

#define MMA(d, a, b) \
    asm volatile("mma.sync.aligned.m16n8k16.row.col.f32.f16.f16.f32 " \
        "{%0,%1,%2,%3}, {%4,%5,%6,%7}, {%8,%9}, {%0,%1,%2,%3};" \
        : "+f"((d)[0]), "+f"((d)[1]), "+f"((d)[2]), "+f"((d)[3]) \
        : "r"((a)[0]), "r"((a)[1]), "r"((a)[2]), "r"((a)[3]), "r"((b)[0]), "r"((b)[1]))

__device__ __forceinline__ void split_store(size_t d, float v)
{
    f16 h = __float2half_rn(v);
    g_hh[d] = h;
    g_hl[d] = __float2half_rn(v - __half2float(h));
}

// ======================= tensor-core GEMM (64x64 tile, BK=64, cp.async) =====
// C[m,n] = sum_k (Ah+Al)[m,k]*W[n,k] + bias[n]   (fp16 2-term split)
__global__ __launch_bounds__(256) void gemm_tc_k(
    const f16* __restrict__ Ah, const f16* __restrict__ Al,
    const f16* __restrict__ W,
    const float* __restrict__ bias, float* __restrict__ C,
    int N, int K, int L, int slotA, int slotC, int mode)
{
    extern __shared__ __align__(16) f16 sm[];
    const uint32_t sbase = smem_u32(sm);

    const int tid  = threadIdx.x;
    const int warp = tid >> 5;
    const int lane = tid & 31;
    const int bm = blockIdx.y << 6;
    const int bn = blockIdx.x << 6;

    const int r0  = tid >> 3;
    const int r1  = 32 + r0;
    const int k16 = tid & 7;

    const int gm0 = bm + r0, gm1 = bm + r1;
    const int ab0 = gm0 / L, ab1 = gm1 / L;
    const size_t aoff0 = (size_t)(ab0 * slotA + (gm0 - ab0 * L)) * K + k16 * 8;
    const size_t aoff1 = (size_t)(ab1 * slotA + (gm1 - ab1 * L)) * K + k16 * 8;
    const size_t woff0 = (size_t)(bn + r0) * K + k16 * 8;
    const size_t woff1 = (size_t)(bn + r1) * K + k16 * 8;

    const uint32_t dA0 = sbase + (0 * GS_MAT + r0 * GS_ROW + k16 * 8) * 2;
    const uint32_t dA1 = sbase + (0 * GS_MAT + r1 * GS_ROW + k16 * 8) * 2;
    const uint32_t dB0 = sbase + (1 * GS_MAT + r0 * GS_ROW + k16 * 8) * 2;
    const uint32_t dB1 = sbase + (1 * GS_MAT + r1 * GS_ROW + k16 * 8) * 2;
    const uint32_t dW0 = sbase + (2 * GS_MAT + r0 * GS_ROW + k16 * 8) * 2;
    const uint32_t dW1 = sbase + (2 * GS_MAT + r1 * GS_ROW + k16 * 8) * 2;

    const int warpM = (warp >> 1) << 4;
    const int warpN = (warp & 1) << 5;
    const int aRow = (lane & 15);
    const int aKof = (lane >> 4) << 3;
    const uint32_t adrAh = sbase + (0 * GS_MAT + (warpM + aRow) * GS_ROW + aKof) * 2;
    const uint32_t adrAl = sbase + (1 * GS_MAT + (warpM + aRow) * GS_ROW + aKof) * 2;
    const int bRow = (lane & 7) + ((lane >> 4) << 3);
    const int bKof = ((lane >> 3) & 1) << 3;
    const uint32_t adrW0 = sbase + (2 * GS_MAT + (warpN + bRow) * GS_ROW + bKof) * 2;
    const uint32_t adrW1 = adrW0 + 16 * GS_ROW * 2;

    float acc[4][4];
    #pragma unroll
    for (int nt = 0; nt < 4; nt++)
        #pragma unroll
        for (int j = 0; j < 4; j++) acc[nt][j] = 0.f;

    const int nc = K >> 6;

    {
        CP16(dA0, Ah + aoff0); CP16(dA1, Ah + aoff1);
        CP16(dB0, Al + aoff0); CP16(dB1, Al + aoff1);
        CP16(dW0, W + woff0);  CP16(dW1, W + woff1);
        CP_COMMIT();
    }

    for (int c = 0; c < nc; c++) {
        const uint32_t bufo = (c & 1) ? (uint32_t)(GS_BUF * 2) : 0u;
        if (c + 1 < nc) {
            const uint32_t nbo = ((c + 1) & 1) ? (uint32_t)(GS_BUF * 2) : 0u;
            const int ko = (c + 1) << 6;
            CP16(dA0 + nbo, Ah + aoff0 + ko); CP16(dA1 + nbo, Ah + aoff1 + ko);
            CP16(dB0 + nbo, Al + aoff0 + ko); CP16(dB1 + nbo, Al + aoff1 + ko);
            CP16(dW0 + nbo, W + woff0 + ko);  CP16(dW1 + nbo, W + woff1 + ko);
            CP_COMMIT();
            CP_WAIT(1);
        } else {
            CP_WAIT(0);
        }
        __syncthreads();

        #pragma unroll
        for (int ks = 0; ks < 4; ks++) {
            const uint32_t kb = bufo + ks * 32;
            uint32_t ah[4], al[4];
            LDM4(ah, adrAh + kb);
            LDM4(al, adrAl + kb);
            uint32_t bw[4][2];
            {
                uint32_t t[4];
                LDM4(t, adrW0 + kb);
                bw[0][0] = t[0]; bw[0][1] = t[1]; bw[1][0] = t[2]; bw[1][1] = t[3];
                LDM4(t, adrW1 + kb);
                bw[2][0] = t[0]; bw[2][1] = t[1]; bw[3][0] = t[2]; bw[3][1] = t[3];
            }
            #pragma unroll
            for (int nt = 0; nt < 4; nt++) {
                MMA(acc[nt], ah, bw[nt]);
                MMA(acc[nt], al, bw[nt]);
            }
        }
        __syncthreads();
    }

    // ---- epilogue ----
    const int cn = bn + warpN + ((lane & 3) << 1);
    #pragma unroll
    for (int half = 0; half < 2; half++) {
        const int m = bm + warpM + (lane >> 2) + half * 8;
        const int b = m / L;
        const int i = m - b * L;
        float* cp = C + (size_t)(b * slotC + i) * N + cn;
        #pragma unroll
        for (int nt = 0; nt < 4; nt++) {
            float2 o;
            o.x = acc[nt][half * 2 + 0] + bias[cn + nt * 8];
            o.y = acc[nt][half * 2 + 1] + bias[cn + nt * 8 + 1];
            *(float2*)(cp + nt * 8) = o;
            if (mode == EP_SC0 && m < NB) {
                size_t d = (size_t)m * NSTEP * NE + cn + nt * 8;
                g_h[d] = o.x; g_h[d + 1] = o.y;
                split_store(d, o.x); split_store(d + 1, o.y);
            }
        }
    }
}

// ======================= fp32 -> fp16 (weights) / fp16 hi+lo (seq) =============
__global__ void conv_all_k(const float* __restrict__ Win, const float* __restrict__ ipw,
                           const float* __restrict__ aow, const float* __restrict__ ffw,
                           const float* __restrict__ seq)
{
    const int nth = gridDim.x * 256;
    for (int idx = blockIdx.x * 256 + threadIdx.x; idx < CONV_TOT; idx += nth) {
        if (idx < WTOT) {
            float x;
            if (idx < OFF_IPW)      x = Win[idx];
            else if (idx < OFF_AOW) x = ipw[idx - OFF_IPW];
            else if (idx < OFF_FFW) x = aow[idx - OFF_AOW];
            else                    x = ffw[idx - OFF_FFW];
            g_w[idx] = __float2half_rn(x);
        } else {
            int i2 = idx - WTOT;
            float x = seq[i2];
            f16 h = __float2half_rn(x);
            g_sh[i2] = h;
            g_sl[i2] = __float2half_rn(x - __half2float(h));
        }
    }
}

__device__ __forceinline__ void scatter_one(int t, int j)
{
    int b = j >> 9, e = j & 511;
    float x = g_X[((size_t)t * NB + b) * NE + e];
    size_t d = ((size_t)b * NSTEP + t) * NE + e;
    g_h[d] = x;
    split_store(d, x);
}

// ---- per (batch, head) attention; rows padded to 65 floats ----
__global__ __launch_bounds__(256) void attn_k(int seqL)
{
    __shared__ float q_s[16][65], k_s[16][65], v_s[16][65];
    __shared__ float p_s[16][17];
    int blk = blockIdx.x; int b = blk >> 3; int hh = blk & 7;
    int tid = threadIdx.x;
    const float* base = g_qkv + (size_t)b * NSTEP * 1536 + hh * 64;
    for (int e = tid; e < 1024; e += 256) {
        int i = e >> 6, d = e & 63;
        if (i < seqL) {
            const float* p = base + (size_t)i * 1536 + d;
            q_s[i][d] = p[0];
            k_s[i][d] = p[512];
            v_s[i][d] = p[1024];
        }
    }
    __syncthreads();
    int si = tid >> 4, sj = tid & 15;
    if (si < seqL && sj < seqL) {
        float s = 0.f;
        #pragma unroll
        for (int d = 0; d < 64; d++) s += q_s[si][d] * k_s[sj][d];
        p_s[si][sj] = s * 0.125f;
    }
    __syncthreads();
    if (tid < seqL) {
        float mx = -1e30f;
        for (int j = 0; j < seqL; j++) mx = fmaxf(mx, p_s[tid][j]);
        float sum = 0.f;
        for (int j = 0; j < seqL; j++) { float e = expf(p_s[tid][j] - mx); p_s[tid][j] = e; sum += e; }
        float inv = 1.f / sum;
        for (int j = 0; j < seqL; j++) p_s[tid][j] *= inv;
    }
    __syncthreads();
    int qi = tid >> 4, d0 = (tid & 15) << 2;
    if (qi < seqL) {
        float o[4] = {0, 0, 0, 0};
        for (int j = 0; j < seqL; j++) {
            float p = p_s[qi][j];
            o[0] += p * v_s[j][d0];     o[1] += p * v_s[j][d0 + 1];
            o[2] += p * v_s[j][d0 + 2]; o[3] += p * v_s[j][d0 + 3];
        }
        size_t d = ((size_t)b * NSTEP + qi) * NE + hh * 64 + d0;
        #pragma unroll
        for (int k = 0; k < 4; k++) {
            f16 h = __float2half_rn(o[k]);
            g_ah[d + k] = h;
            g_al[d + k] = __float2half_rn(o[k] - __half2float(h));
        }
    }
}

// ---- h = LN(h + tmp)*scale + bias (+ split); optional fused outproj / scatter ----
__global__ __launch_bounds__(256) void resid_ln_k(
    const float* __restrict__ sc, const float* __restrict__ bi, int seqL,
    int fuse_out, int t, int do_scatter,
    const float* __restrict__ Wout, const float* __restrict__ b_out,
    float* __restrict__ out)
{
    const int tid = threadIdx.x;
    const int r = blockIdx.x;
    const int nrows = NB * seqL;
    if (r >= nrows) {
        for (int e = (r - nrows) * 256 + tid; e < NB * NE; e += 64 * 256)
            scatter_one(t + 1, e);
        return;
    }
    int b = r / seqL; int i = r - b * seqL;
    size_t rowo = ((size_t)b * NSTEP + i) * NE;
    float* hp = g_h + rowo;
    const float* tp = g_tmp + rowo;
    float y0 = hp[tid] + tp[tid];
    float y1 = hp[tid + 256] + tp[tid + 256];
    float s = y0 + y1, ss = y0 * y0 + y1 * y1;
    __shared__ float shs[8], shq[8];
    __shared__ float mu_sh, inv_sh;
    __shared__ __align__(16) float rowbuf[512];
    int lane = tid & 31, w = tid >> 5;
    #pragma unroll
    for (int o = 16; o > 0; o >>= 1) {
        s  += __shfl_down_sync(0xffffffffu, s, o);
        ss += __shfl_down_sync(0xffffffffu, ss, o);
    }
    if (lane == 0) { shs[w] = s; shq[w] = ss; }
    __syncthreads();
    if (tid == 0) {
        float ts = 0, tq = 0;
        #pragma unroll
        for (int k = 0; k < 8; k++) { ts += shs[k]; tq += shq[k]; }
        float mu = ts * (1.f / 512.f);
        float var = tq * (1.f / 512.f) - mu * mu;
        mu_sh = mu; inv_sh = rsqrtf(var + 1e-5f);
    }
    __syncthreads();
    float mu = mu_sh, inv = inv_sh;
    float v0 = (y0 - mu) * inv * sc[tid]       + bi[tid];
    float v1 = (y1 - mu) * inv * sc[tid + 256] + bi[tid + 256];
    hp[tid] = v0; hp[tid + 256] = v1;
    split_store(rowo + tid, v0);
    split_store(rowo + tid + 256, v1);

    if (fuse_out && i == t) {
        rowbuf[tid] = v0; rowbuf[tid + 256] = v1;
        __syncthreads();
        if (tid < NOUT) {
            const float4* wr = (const float4*)(Wout + (size_t)tid * NE);
            const float4* rb = (const float4*)rowbuf;
            float acc = 0.f;
            #pragma unroll 8
            for (int e = 0; e < 128; e++) {
                float4 aa = rb[e], ww = wr[e];
                acc += aa.x * ww.x + aa.y * ww.y + aa.z * ww.z + aa.w * ww.w;
            }
            out[((size_t)t * NB + b) * NOUT + tid] = acc + b_out[tid];
        }
    }
}

// ---- write new_h ----
__global__ void assemble_k(const float* __restrict__ hstate, float* __restrict__ outh)
{
    int idx = blockIdx.x * 256 + threadIdx.x;
    if (idx >= NB * NMEM) return;
    int b = idx / NMEM; int j = idx - b * NMEM;
    float v;
    if (j < NSTEP * NE)      v = g_h[(size_t)b * NSTEP * NE + j];
    else if (j < NMEM - 1)   v = hstate[idx];
    else                     v = (float)((int)hstate[idx] + NSTEP);
    outh[idx] = v;
}

extern "C" void kernel_launch(void* const* d_in, const int* in_sizes, int n_in,
                              void* d_out, int out_size)
{
    (void)in_sizes; (void)n_in; (void)out_size;
    const float* seq   = (const float*)d_in[0];
    const float* hst   = (const float*)d_in[1];
    const float* Win   = (const float*)d_in[2];
    const float* b_in  = (const float*)d_in[3];
    const float* Wout  = (const float*)d_in[4];
    const float* b_out = (const float*)d_in[5];
    const float* ipw   = (const float*)d_in[6];
    const float* ipb   = (const float*)d_in[7];
    const float* aow   = (const float*)d_in[8];
    const float* aob   = (const float*)d_in[9];
    const float* l1s   = (const float*)d_in[10];
    const float* l1b   = (const float*)d_in[11];
    const float* l2s   = (const float*)d_in[12];
    const float* l2b   = (const float*)d_in[13];
    const float* ffw   = (const float*)d_in[14];
    const float* ffb   = (const float*)d_in[15];
    float* out = (float*)d_out;

    cudaFuncSetAttribute(gemm_tc_k, cudaFuncAttributeMaxDynamicSharedMemorySize, GS_BYTES);

    float *pX, *pqkv, *ptmp;
    f16 *phh, *phl, *pah, *pal, *psh, *psl, *pw;
    cudaGetSymbolAddress((void**)&pX,   g_X);
    cudaGetSymbolAddress((void**)&pqkv, g_qkv);
    cudaGetSymbolAddress((void**)&ptmp, g_tmp);
    cudaGetSymbolAddress((void**)&phh,  g_hh);
    cudaGetSymbolAddress((void**)&phl,  g_hl);
    cudaGetSymbolAddress((void**)&pah,  g_ah);
    cudaGetSymbolAddress((void**)&pal,  g_al);
    cudaGetSymbolAddress((void**)&psh,  g_sh);
    cudaGetSymbolAddress((void**)&psl,  g_sl);
    cudaGetSymbolAddress((void**)&pw,   g_w);

    conv_all_k<<<512, 256>>>(Win, ipw, aow, ffw, seq);

    // X = seq @ Win^T + b_in (M=2048 contiguous, N=512, K=256) + scatter(0) fused
    gemm_tc_k<<<dim3(NE / 64, (NSTEP * NB) / 64), 256, GS_BYTES>>>(
        psh, psl, pw + OFF_WIN, b_in, pX,
        NE, NIN, NSTEP * NB, 0, 0, EP_SC0);

    for (int t = 0; t < NSTEP; t++) {
        int Lq = t + 1;
        int mt = (NB * Lq) / 64;      // 2*Lq

        for (int l = 0; l < NLAY; l++) {
            gemm_tc_k<<<dim3(3 * NE / 64, mt), 256, GS_BYTES>>>(
                phh, phl, pw + OFF_IPW + (size_t)l * 3 * NE * NE,
                ipb + l * 3 * NE, pqkv, 3 * NE, NE, Lq, NSTEP, NSTEP, EP_NONE);
            attn_k<<<NB * NH, 256>>>(Lq);
            gemm_tc_k<<<dim3(NE / 64, mt), 256, GS_BYTES>>>(
                pah, pal, pw + OFF_AOW + (size_t)l * NE * NE,
                aob + l * NE, ptmp, NE, NE, Lq, NSTEP, NSTEP, EP_NONE);
            resid_ln_k<<<NB * Lq, 256>>>(l1s + l * NE, l1b + l * NE, Lq,
                                         0, t, 0, nullptr, nullptr, nullptr);
            gemm_tc_k<<<dim3(NE / 64, mt), 256, GS_BYTES>>>(
                phh, phl, pw + OFF_FFW + (size_t)l * NE * NE,
                ffb + l * NE, ptmp, NE, NE, Lq, NSTEP, NSTEP, EP_NONE);
            int fo = (l == 1) ? 1 : 0;
            int dsc = (l == 1 && t + 1 < NSTEP) ? 1 : 0;
            resid_ln_k<<<NB * Lq + (dsc ? 64 : 0), 256>>>(
                l2s + l * NE, l2b + l * NE, Lq, fo, t, dsc, Wout, b_out, out);
        }
    }

    assemble_k<<<(NB * NMEM + 255) / 256, 256>>>(hst, out + NSTEP * NB * NOUT);
}